// round 15
// baseline (speedup 1.0000x reference)
#include <cuda_runtime.h>
#include <cuda_bf16.h>
#include <math.h>
#include <stdint.h>

// Problem shape (fixed)
#define T_ 512
#define B_ 64
#define H_ 1024
#define I_ 1024
#define G3H 3072
#define NBLK 24
#define KSPLIT 6
#define GRID_P 144            // persistent CTAs (<=148, 1/SM => all resident)
#define NTHR 512              // 16 warps/CTA

// Recurrence smem offsets (max klen=176, kpad=184)
#define SM_A_HI 0
#define SM_A_LO (128 * 184 * 2)                 // 47104
#define SM_B_HI (2 * 128 * 184 * 2)             // 94208
#define SM_B_LO (SM_B_HI + 176 * 72 * 2)        // 119552
#define SM_TOTAL (SM_B_LO + 176 * 72 * 2)       // 144896

// Phase-1 double-buffered smem: A hi/lo [2][128][24], B hi/lo [2][16][136]
#define P1_APAD 24
#define P1_BPAD 136
#define Q_ABYTES (128 * P1_APAD * 2)            // 6144
#define Q_BBYTES (16 * P1_BPAD * 2)             // 4352
#define Q_A_HI   0
#define Q_A_LO   (2 * Q_ABYTES)                 // 12288
#define Q_B_HI   (4 * Q_ABYTES)                 // 24576
#define Q_B_LO   (Q_B_HI + 2 * Q_BBYTES)        // 33280
#define Q_TOTAL  (Q_B_LO + 2 * Q_BBYTES)        // 41984

// Proj smem (single buffer, round-11 layout)
#define P1_A_HI 0
#define P1_A_LO (128 * P1_APAD * 2)             // 6144
#define P1_B_HI (2 * 128 * P1_APAD * 2)         // 12288
#define P1_B_LO (P1_B_HI + 16 * P1_BPAD * 2)    // 16640
#define P1_TOTAL (P1_B_LO + 16 * P1_BPAD * 2)   // 20992

// Scratch (device globals: allocation-free contract)
__device__ float g_gx[(size_t)T_ * G3H * B_];             // [t][n][b]
__device__ uint32_t g_xp[(size_t)B_ * T_ * I_];           // [b*T+t][i] packed (hi,lo)
__device__ uint32_t g_hhl[(size_t)(T_ + 1) * H_ * B_];    // [slot][k][b] packed (hi,lo)
__device__ float g_gh[(size_t)2 * KSPLIT * G3H * B_];     // [parity][s][n][b]
__device__ unsigned int g_rowflag[NBLK * 32];
__device__ unsigned int g_sliceflag[KSPLIT * 32];

__device__ __forceinline__ uint32_t smem_u32(const void* p) {
    uint32_t a;
    asm("{ .reg .u64 t; cvta.to.shared.u64 t, %1; cvt.u32.u64 %0, t; }"
        : "=r"(a) : "l"(p));
    return a;
}
__device__ __forceinline__ void ldsm_x4(uint32_t* r, uint32_t addr) {
    asm volatile("ldmatrix.sync.aligned.m8n8.x4.shared.b16 {%0,%1,%2,%3}, [%4];"
                 : "=r"(r[0]), "=r"(r[1]), "=r"(r[2]), "=r"(r[3]) : "r"(addr));
}
__device__ __forceinline__ void ldsm_x4_t(uint32_t* r, uint32_t addr) {
    asm volatile("ldmatrix.sync.aligned.m8n8.x4.trans.shared.b16 {%0,%1,%2,%3}, [%4];"
                 : "=r"(r[0]), "=r"(r[1]), "=r"(r[2]), "=r"(r[3]) : "r"(addr));
}
__device__ __forceinline__ void mma_bf16(float* d, const uint32_t* a, const uint32_t* b) {
    asm volatile("mma.sync.aligned.m16n8k16.row.col.f32.bf16.bf16.f32 "
                 "{%0,%1,%2,%3}, {%4,%5,%6,%7}, {%8,%9}, {%0,%1,%2,%3};"
                 : "+f"(d[0]), "+f"(d[1]), "+f"(d[2]), "+f"(d[3])
                 : "r"(a[0]), "r"(a[1]), "r"(a[2]), "r"(a[3]), "r"(b[0]), "r"(b[1]));
}
__device__ __forceinline__ void flag_wait(const unsigned int* p, unsigned int target) {
    unsigned int v;
    do {
        asm volatile("ld.acquire.gpu.global.u32 %0, [%1];" : "=r"(v) : "l"(p) : "memory");
    } while (v < target);
}
__device__ __forceinline__ void flag_arrive(unsigned int* p) {
    asm volatile("red.release.gpu.global.add.u32 [%0], %1;" :: "l"(p), "r"(1u) : "memory");
}
__device__ __forceinline__ float unhl(uint32_t p) {
    return __bfloat162float(__ushort_as_bfloat16((unsigned short)(p & 0xffffu))) +
           __bfloat162float(__ushort_as_bfloat16((unsigned short)(p >> 16)));
}
__device__ __forceinline__ uint32_t packhl(float h) {
    const __nv_bfloat16 hi = __float2bfloat16(h);
    const __nv_bfloat16 lo = __float2bfloat16(h - __bfloat162float(hi));
    return (uint32_t)__bfloat16_as_ushort(hi) | ((uint32_t)__bfloat16_as_ushort(lo) << 16);
}

__global__ void init_kernel() {
    int i = blockIdx.x * blockDim.x + threadIdx.x;
    if (i < H_ * B_) g_hhl[i] = 0u;                // slot 0 = h_{-1} = 0
    if (i < NBLK * 32) g_rowflag[i] = 0u;
    if (i < KSPLIT * 32) g_sliceflag[i] = 0u;
}

// x[b][t][i] fp32 -> packed (hi,lo) bf16 u32
__global__ __launch_bounds__(512) void xconv(const float* __restrict__ x) {
    const size_t idx = (size_t)blockIdx.x * 512 + threadIdx.x;
    if (idx < (size_t)B_ * T_ * I_) g_xp[idx] = packhl(x[idx]);
}

// ---------------------------------------------------------------------------
// Phase-1 bf16 HMMA GEMM, 3-PASS, double-buffered (validated round 14):
// gx[t][n][b] = x @ w_ih^T. Tile 128n x 128bt, grid (24, 256), 512 threads.
// ---------------------------------------------------------------------------
__global__ __launch_bounds__(512) void gemm1_hmma(
    const float* __restrict__ w_ih)   // [3072][1024]
{
    __shared__ char sm[Q_TOTAL];
    const uint32_t smb = smem_u32(sm);
    const int tid = threadIdx.x;
    const int wid = tid >> 5;
    const int lid = tid & 31;
    const int n0 = blockIdx.x * 128;
    const int t0 = blockIdx.y * 2;
    const int wn  = wid >> 1;
    const int wbt = wid & 1;

    const int w_row = tid >> 2;
    const int w_kq  = (tid & 3) * 4;
    const int x_ci  = tid >> 2;
    const int x_kq  = (tid & 3) * 4;
    const int x_b   = x_ci & 63;
    const int x_tt  = x_ci >> 6;
    const float* wp_base = w_ih + (size_t)(n0 + w_row) * I_ + w_kq;
    const uint32_t* xp_base = g_xp + ((size_t)x_b * T_ + (t0 + x_tt)) * I_ + x_kq;

    const uint32_t aA = smb + Q_A_HI +
        (uint32_t)(((wn * 16 + (lid & 15)) * P1_APAD + ((lid >> 4) << 3)) << 1);
    const uint32_t bA = smb + Q_B_HI +
        (uint32_t)(((((lid >> 3) & 1) * 8 + (lid & 7)) * P1_BPAD + wbt * 64 + ((lid >> 4) << 3)) << 1);

    float d[8][4];
#pragma unroll
    for (int nt = 0; nt < 8; ++nt)
#pragma unroll
        for (int q = 0; q < 4; ++q) d[nt][q] = 0.0f;

    auto stage = [&](int buf, const float4& wv, const uint4& xv) {
        __nv_bfloat16* asH = (__nv_bfloat16*)(sm + Q_A_HI + buf * Q_ABYTES);
        __nv_bfloat16* asL = (__nv_bfloat16*)(sm + Q_A_LO + buf * Q_ABYTES);
        __nv_bfloat16* bsH = (__nv_bfloat16*)(sm + Q_B_HI + buf * Q_BBYTES);
        __nv_bfloat16* bsL = (__nv_bfloat16*)(sm + Q_B_LO + buf * Q_BBYTES);
        const float wf[4] = {wv.x, wv.y, wv.z, wv.w};
#pragma unroll
        for (int j = 0; j < 4; ++j) {
            const __nv_bfloat16 hi = __float2bfloat16(wf[j]);
            asH[w_row * P1_APAD + w_kq + j] = hi;
            asL[w_row * P1_APAD + w_kq + j] =
                __float2bfloat16(wf[j] - __bfloat162float(hi));
        }
        const uint32_t xu[4] = {xv.x, xv.y, xv.z, xv.w};
#pragma unroll
        for (int j = 0; j < 4; ++j) {
            bsH[(x_kq + j) * P1_BPAD + x_ci] =
                __ushort_as_bfloat16((unsigned short)(xu[j] & 0xffffu));
            bsL[(x_kq + j) * P1_BPAD + x_ci] =
                __ushort_as_bfloat16((unsigned short)(xu[j] >> 16));
        }
    };

    {
        const float4 wv0 = *(const float4*)(wp_base);
        const uint4  xv0 = *(const uint4*)(xp_base);
        stage(0, wv0, xv0);
    }
    __syncthreads();

    for (int kc = 0; kc < 64; ++kc) {
        float4 wv; uint4 xv;
        const bool more = (kc + 1 < 64);
        if (more) {
            wv = *(const float4*)(wp_base + (kc + 1) * 16);
            xv = *(const uint4*)(xp_base + (kc + 1) * 16);
        }

        const uint32_t aOff = (uint32_t)((kc & 1) * Q_ABYTES);
        const uint32_t bOff = (uint32_t)((kc & 1) * Q_BBYTES);
        uint32_t aH[4], aL[4], bh[16], bl[16];
        ldsm_x4(aH, aA + aOff);
        ldsm_x4(aL, aA + aOff + (Q_A_LO - Q_A_HI));
#pragma unroll
        for (int q = 0; q < 4; ++q) ldsm_x4_t(&bh[q * 4], bA + bOff + q * 32);
#pragma unroll
        for (int q = 0; q < 4; ++q)
            ldsm_x4_t(&bl[q * 4], bA + bOff + (Q_B_LO - Q_B_HI) + q * 32);

#pragma unroll
        for (int nt = 0; nt < 8; ++nt) mma_bf16(d[nt], aH, &bh[nt * 2]);
#pragma unroll
        for (int nt = 0; nt < 8; ++nt) mma_bf16(d[nt], aH, &bl[nt * 2]);
#pragma unroll
        for (int nt = 0; nt < 8; ++nt) mma_bf16(d[nt], aL, &bh[nt * 2]);

        if (more) stage((kc + 1) & 1, wv, xv);
        __syncthreads();
    }

    {
        const int g = lid >> 2;
        const int q = lid & 3;
        const int n = n0 + wn * 16 + g;
        const int tcur = t0 + wbt;
        float* gx0 = g_gx + ((size_t)tcur * G3H + n) * B_;
        float* gx1 = g_gx + ((size_t)tcur * G3H + n + 8) * B_;
#pragma unroll
        for (int nt = 0; nt < 8; ++nt) {
            const int b = nt * 8 + q * 2;
            *(float2*)(gx0 + b) = make_float2(d[nt][0], d[nt][1]);
            *(float2*)(gx1 + b) = make_float2(d[nt][2], d[nt][3]);
        }
    }
}

// ---------------------------------------------------------------------------
// Persistent bf16-MMA recurrence — warp-granular flags (rowflag counts 96,
// sliceflag 384 per step), register double-buffered mainloop, 2 block syncs.
// ---------------------------------------------------------------------------
extern __shared__ char dynsm[];

#define LDCHUNK(S, kc) do { \
    const uint32_t aA_ = aAddr0 + (uint32_t)((kc) * 32); \
    const uint32_t bA_ = bAddr0 + (uint32_t)((kc) * 2304); \
    ldsm_x4(aH##S, aA_); \
    ldsm_x4(aL##S, aA_ + A_LO_OFF); \
    ldsm_x4_t(bh##S,     bA_); \
    ldsm_x4_t(bh##S + 4, bA_ + 32); \
    ldsm_x4_t(bl##S,     bA_ + B_LO_OFF); \
    ldsm_x4_t(bl##S + 4, bA_ + B_LO_OFF + 32); \
} while (0)

#define MMACHUNK(S) do { \
    _Pragma("unroll") \
    for (int nt = 0; nt < 4; ++nt) mma_bf16(d[nt], aH##S, &bh##S[nt * 2]); \
    _Pragma("unroll") \
    for (int nt = 0; nt < 4; ++nt) mma_bf16(d[nt], aH##S, &bl##S[nt * 2]); \
    _Pragma("unroll") \
    for (int nt = 0; nt < 4; ++nt) mma_bf16(d[nt], aL##S, &bh##S[nt * 2]); \
} while (0)

__global__ __launch_bounds__(NTHR) void gru_persistent(
    const float* __restrict__ w_hh)   // [3072][1024]
{
    char* sm = dynsm;
    const uint32_t smem_base = smem_u32(sm);
    const int tid = threadIdx.x;
    const int wid = tid >> 5;
    const int lid = tid & 31;
    const int bid = blockIdx.x;
    const int nbk = bid % NBLK;
    const int s   = bid / NBLK;
    const int n0  = nbk * 128;
    const int kbase = (s < 4) ? s * 176 : 704 + (s - 4) * 160;
    const int klen  = (s < 4) ? 176 : 160;
    const int nkt   = klen >> 4;
    const int kpad  = klen + 8;

    {
        __nv_bfloat16* wsH = (__nv_bfloat16*)(sm + SM_A_HI);
        __nv_bfloat16* wsL = (__nv_bfloat16*)(sm + SM_A_LO);
        for (int i = tid; i < 128 * klen; i += NTHR) {
            const int row = i / klen;
            const int k   = i - row * klen;
            const float w = w_hh[(size_t)(n0 + row) * H_ + kbase + k];
            const __nv_bfloat16 hi = __float2bfloat16(w);
            wsH[row * kpad + k] = hi;
            wsL[row * kpad + k] = __float2bfloat16(w - __bfloat162float(hi));
        }
    }

    const int wn = wid >> 1;
    const int wb = wid & 1;
    const uint32_t aAddr0 = smem_base + SM_A_HI +
        (uint32_t)(((wn * 16 + (lid & 15)) * kpad + ((lid >> 4) << 3)) << 1);
    const uint32_t bAddr0 = smem_base + SM_B_HI +
        (uint32_t)(((((lid >> 3) & 1) * 8 + (lid & 7)) * 72 + wb * 32 + ((lid >> 4) << 3)) << 1);
    const uint32_t A_LO_OFF = SM_A_LO - SM_A_HI;
    const uint32_t B_LO_OFF = SM_B_LO - SM_B_HI;

    __nv_bfloat16* hsH = (__nv_bfloat16*)(sm + SM_B_HI);
    __nv_bfloat16* hsL = (__nv_bfloat16*)(sm + SM_B_LO);

    // Gate partition: element e -> (j = kbase + e/64, b = e%64); 1 elem/thread
    const int nelem = klen * 64;
    const int chunk = (nelem + NBLK - 1) / NBLK;
    const int e_lo = nbk * chunk;
    const int e_hi = (e_lo + chunk < nelem) ? (e_lo + chunk) : nelem;
    const int e0 = e_lo + tid;
    const bool v0 = e0 < e_hi;
    const int j0 = kbase + (e0 >> 6), b0v = e0 & 63;

    // Per-WARP rowflag wait set (this warp's 32 consecutive elements)
    const int we0 = e_lo + wid * 32;
    const bool wvalid = we0 < e_hi;
    int wjb_lo = 0, wnjb = 0;
    if (wvalid) {
        int we1 = we0 + 31;
        if (we1 > e_hi - 1) we1 = e_hi - 1;
        wjb_lo = (kbase + (we0 >> 6)) >> 7;
        const int wjb_hi = (kbase + (we1 >> 6)) >> 7;
        wnjb = wjb_hi - wjb_lo + 1;               // 1..2
    }
    const int wnfl = wnjb * 3;

    for (int t = 0; t < T_; ++t) {
        const int par = t & 1;

        // ---- prefetch gx gate operands (flag-independent)
        float gr0 = 0.f, gz0 = 0.f, gn0 = 0.f;
        {
            const float* gxt = g_gx + (size_t)t * G3H * B_;
            if (v0) {
                gr0 = gxt[(size_t)j0 * B_ + b0v];
                gz0 = gxt[(size_t)(1024 + j0) * B_ + b0v];
                gn0 = gxt[(size_t)(2048 + j0) * B_ + b0v];
            }
        }

        // all warps done reading smem from previous mainloop before restaging
        __syncthreads();

        // ---- per-warp wait: h slice s (slot t) ready (384 gate-warp arrivals/step)
        if (lid == 0) flag_wait(&g_sliceflag[s * 32], 384u * (unsigned)t);
        __syncwarp();

        // ---- stage h slice: packed (hi,lo) -> two smem planes
        {
            const uint32_t* hp = g_hhl + (size_t)t * H_ * B_;
            for (int i = tid; i < klen * 32; i += NTHR) {
                const int k  = i >> 5;
                const int bp = (i & 31) << 1;
                const uint2 v = __ldcg((const uint2*)(hp + (size_t)(kbase + k) * B_ + bp));
                *(uint32_t*)&hsH[k * 72 + bp] = __byte_perm(v.x, v.y, 0x5410);
                *(uint32_t*)&hsL[k * 72 + bp] = __byte_perm(v.x, v.y, 0x7632);
            }
        }
        __syncthreads();

        // ---- mainloop: register double-buffered, 3 HMMA passes per chunk
        float d[4][4];
#pragma unroll
        for (int nt = 0; nt < 4; ++nt)
#pragma unroll
            for (int q = 0; q < 4; ++q) d[nt][q] = 0.0f;

        {
            uint32_t aHA[4], aLA[4], bhA[8], blA[8];
            uint32_t aHB[4], aLB[4], bhB[8], blB[8];
            LDCHUNK(A, 0);
            for (int kc = 0; kc < nkt; kc += 2) {
                if (kc + 1 < nkt) LDCHUNK(B, kc + 1);
                MMACHUNK(A);
                if (kc + 1 < nkt) {
                    if (kc + 2 < nkt) LDCHUNK(A, kc + 2);
                    MMACHUNK(B);
                }
            }
        }

        // ---- epilogue: D(n,b) -> g_gh[par][s][n][b]; per-warp rowflag arrive
        {
            float* gh = g_gh + ((size_t)par * KSPLIT + s) * G3H * B_;
            const int g = lid >> 2;
            const int q = lid & 3;
            const int nb = n0 + wn * 16 + g;
#pragma unroll
            for (int nt = 0; nt < 4; ++nt) {
                const int b = wb * 32 + nt * 8 + q * 2;
                *(float2*)&gh[(size_t)nb * B_ + b]       = make_float2(d[nt][0], d[nt][1]);
                *(float2*)&gh[(size_t)(nb + 8) * B_ + b] = make_float2(d[nt][2], d[nt][3]);
            }
        }
        __syncwarp();
        if (lid == 0) flag_arrive(&g_rowflag[nbk * 32]);   // 96 arrivals/step

        // ---- per-warp wait for the gh rows THIS warp's gate elements need
        if (wvalid && lid < wnfl) {
            const int jb = wjb_lo + (lid % wnjb);
            const int g8 = (lid / wnjb) * 8;
            flag_wait(&g_rowflag[(jb + g8) * 32], 96u * (unsigned)(t + 1));
        }
        __syncwarp();

        // ---- gate: reduce 6 split partials, activations, write h slot t+1
        if (v0) {
            const float* ghp = g_gh + (size_t)par * KSPLIT * G3H * B_;
            const uint32_t* hprev = g_hhl + (size_t)t * H_ * B_;
            uint32_t* hout = g_hhl + (size_t)(t + 1) * H_ * B_;
            float sr = 0.f, sz = 0.f, sn = 0.f;
#pragma unroll
            for (int ss = 0; ss < KSPLIT; ++ss) {
                const float* p = ghp + (size_t)ss * G3H * B_;
                sr += __ldcg(p + (size_t)j0 * B_ + b0v);
                sz += __ldcg(p + (size_t)(1024 + j0) * B_ + b0v);
                sn += __ldcg(p + (size_t)(2048 + j0) * B_ + b0v);
            }
            const float r = 1.0f / (1.0f + expf(-(gr0 + sr)));
            const float z = 1.0f / (1.0f + expf(-(gz0 + sz)));
            const float n = tanhf(gn0 + r * sn);
            const float hp = unhl(hprev[(size_t)j0 * B_ + b0v]);
            hout[(size_t)j0 * B_ + b0v] = packhl((1.0f - z) * n + z * hp);
        }
        __syncwarp();
        if (lid == 0) flag_arrive(&g_sliceflag[s * 32]);   // 384 arrivals/step
    }
}

// ---------------------------------------------------------------------------
// Phase-3 bf16 HMMA projection, 3-PASS (validated round 11/14)
// ---------------------------------------------------------------------------
__global__ __launch_bounds__(512) void proj_hmma(
    const float* __restrict__ wp,     // [1024][1024]
    float* __restrict__ out)          // [64][512][1024]
{
    __shared__ char sm[P1_TOTAL];
    const uint32_t smb = smem_u32(sm);
    const int tid = threadIdx.x;
    const int wid = tid >> 5;
    const int lid = tid & 31;
    const int n0 = blockIdx.x * 128;
    const int t0 = blockIdx.y * 2;
    const int wn  = wid >> 1;
    const int wbt = wid & 1;

    __nv_bfloat16* asH = (__nv_bfloat16*)(sm + P1_A_HI);
    __nv_bfloat16* asL = (__nv_bfloat16*)(sm + P1_A_LO);
    __nv_bfloat16* bsH = (__nv_bfloat16*)(sm + P1_B_HI);
    __nv_bfloat16* bsL = (__nv_bfloat16*)(sm + P1_B_LO);

    const int w_row = tid >> 2;
    const int w_kq  = (tid & 3) * 4;
    const float* wp_base = wp + (size_t)(n0 + w_row) * H_ + w_kq;

    const int i0 = tid, i1 = tid + 512;
    const int s_tt0 = i0 >> 9, s_k0 = (i0 >> 5) & 15, s_bp0 = (i0 & 31) << 1;
    const int s_tt1 = i1 >> 9, s_k1 = (i1 >> 5) & 15, s_bp1 = (i1 & 31) << 1;
    const uint32_t* hb0 = g_hhl + (size_t)(t0 + s_tt0 + 1) * H_ * B_ + s_k0 * B_ + s_bp0;
    const uint32_t* hb1 = g_hhl + (size_t)(t0 + s_tt1 + 1) * H_ * B_ + s_k1 * B_ + s_bp1;

    const uint32_t aA = smb + P1_A_HI +
        (uint32_t)(((wn * 16 + (lid & 15)) * P1_APAD + ((lid >> 4) << 3)) << 1);
    const uint32_t bA = smb + P1_B_HI +
        (uint32_t)(((((lid >> 3) & 1) * 8 + (lid & 7)) * P1_BPAD + wbt * 64 + ((lid >> 4) << 3)) << 1);
    const uint32_t A_LO = P1_A_LO - P1_A_HI;
    const uint32_t B_LO = P1_B_LO - P1_B_HI;

    float d[8][4];
#pragma unroll
    for (int nt = 0; nt < 8; ++nt)
#pragma unroll
        for (int q = 0; q < 4; ++q) d[nt][q] = 0.0f;

    float4 wv = *(const float4*)(wp_base);
    uint2  hv0 = __ldcg((const uint2*)hb0);
    uint2  hv1 = __ldcg((const uint2*)hb1);

    for (int kc = 0; kc < 64; ++kc) {
        __syncthreads();
        {
            const float wf[4] = {wv.x, wv.y, wv.z, wv.w};
#pragma unroll
            for (int j = 0; j < 4; ++j) {
                const __nv_bfloat16 hi = __float2bfloat16(wf[j]);
                asH[w_row * P1_APAD + w_kq + j] = hi;
                asL[w_row * P1_APAD + w_kq + j] =
                    __float2bfloat16(wf[j] - __bfloat162float(hi));
            }
            *(uint32_t*)&bsH[s_k0 * P1_BPAD + s_tt0 * 64 + s_bp0] = __byte_perm(hv0.x, hv0.y, 0x5410);
            *(uint32_t*)&bsL[s_k0 * P1_BPAD + s_tt0 * 64 + s_bp0] = __byte_perm(hv0.x, hv0.y, 0x7632);
            *(uint32_t*)&bsH[s_k1 * P1_BPAD + s_tt1 * 64 + s_bp1] = __byte_perm(hv1.x, hv1.y, 0x5410);
            *(uint32_t*)&bsL[s_k1 * P1_BPAD + s_tt1 * 64 + s_bp1] = __byte_perm(hv1.x, hv1.y, 0x7632);
        }
        __syncthreads();
        if (kc + 1 < 64) {
            wv  = *(const float4*)(wp_base + (kc + 1) * 16);
            hv0 = __ldcg((const uint2*)(hb0 + (size_t)(kc + 1) * 16 * B_));
            hv1 = __ldcg((const uint2*)(hb1 + (size_t)(kc + 1) * 16 * B_));
        }

        uint32_t aH[4], aL[4], bh[16], bl[16];
        ldsm_x4(aH, aA);
        ldsm_x4(aL, aA + A_LO);
#pragma unroll
        for (int q = 0; q < 4; ++q) ldsm_x4_t(&bh[q * 4], bA + q * 32);
#pragma unroll
        for (int q = 0; q < 4; ++q) ldsm_x4_t(&bl[q * 4], bA + B_LO + q * 32);

#pragma unroll
        for (int nt = 0; nt < 8; ++nt) mma_bf16(d[nt], aH, &bh[nt * 2]);
#pragma unroll
        for (int nt = 0; nt < 8; ++nt) mma_bf16(d[nt], aH, &bl[nt * 2]);
#pragma unroll
        for (int nt = 0; nt < 8; ++nt) mma_bf16(d[nt], aL, &bh[nt * 2]);
    }

    {
        const int g = lid >> 2;
        const int q = lid & 3;
        const int n = n0 + wn * 16 + g;
        const int tcur = t0 + wbt;
#pragma unroll
        for (int nt = 0; nt < 8; ++nt) {
            const int b = nt * 8 + q * 2;
            out[((size_t)b * T_ + tcur) * H_ + n]           = d[nt][0];
            out[((size_t)(b + 1) * T_ + tcur) * H_ + n]     = d[nt][1];
            out[((size_t)b * T_ + tcur) * H_ + n + 8]       = d[nt][2];
            out[((size_t)(b + 1) * T_ + tcur) * H_ + n + 8] = d[nt][3];
        }
    }
}

// ---------------------------------------------------------------------------
// kernel_launch — 5 graph nodes, graph-capturable, allocation-free.
// Inputs: x[64,512,1024], w_ih[3072,1024], w_hh[3072,1024], w_proj[1024,1024].
// ---------------------------------------------------------------------------
extern "C" void kernel_launch(void* const* d_in, const int* in_sizes, int n_in,
                              void* d_out, int out_size) {
    const float* x      = (const float*)d_in[0];
    const float* w_ih   = (const float*)d_in[1];
    const float* w_hh   = (const float*)d_in[2];
    const float* w_proj = (const float*)d_in[3];
    float* out = (float*)d_out;

    cudaFuncSetAttribute(gru_persistent,
                         cudaFuncAttributeMaxDynamicSharedMemorySize, SM_TOTAL);

    init_kernel<<<(H_ * B_ + 255) / 256, 256>>>();

    // x -> packed bf16 (hi,lo)
    xconv<<<(B_ * T_ * I_) / 512, 512>>>(x);

    // Phase 1 (HMMA 3-pass, double-buffered): gx[t][n][b] = x @ w_ih^T
    {
        dim3 grid(G3H / 128, T_ / 2);
        gemm1_hmma<<<grid, 512>>>(w_ih);
    }

    // Phase 2: whole recurrence, ONE persistent 512-thread kernel (launch #4)
    gru_persistent<<<GRID_P, NTHR, SM_TOTAL>>>(w_hh);

    // Phase 3 (HMMA 3-pass): out[b][t][n] = h[t+1] @ w_proj^T
    {
        dim3 grid(H_ / 128, T_ / 2);
        proj_hmma<<<grid, 512>>>(w_proj, out);
    }
}

// round 16
// speedup vs baseline: 1.1318x; 1.1318x over previous
#include <cuda_runtime.h>
#include <cuda_bf16.h>
#include <math.h>
#include <stdint.h>

// Problem shape (fixed)
#define T_ 512
#define B_ 64
#define H_ 1024
#define I_ 1024
#define G3H 3072
#define NBLK 24
#define KSPLIT 6
#define GRID_P 144            // persistent CTAs (<=148, 1/SM => all resident)
#define NTHR 512              // 16 warps/CTA

// Recurrence smem offsets (max klen=176, kpad=184)
#define SM_A_HI 0
#define SM_A_LO (128 * 184 * 2)                 // 47104
#define SM_B_HI (2 * 128 * 184 * 2)             // 94208
#define SM_B_LO (SM_B_HI + 176 * 72 * 2)        // 119552
#define SM_TOTAL (SM_B_LO + 176 * 72 * 2)       // 144896

// Phase-1 double-buffered smem: A hi/lo [2][128][24], B hi/lo [2][16][136]
#define P1_APAD 24
#define P1_BPAD 136
#define Q_ABYTES (128 * P1_APAD * 2)            // 6144
#define Q_BBYTES (16 * P1_BPAD * 2)             // 4352
#define Q_A_HI   0
#define Q_A_LO   (2 * Q_ABYTES)                 // 12288
#define Q_B_HI   (4 * Q_ABYTES)                 // 24576
#define Q_B_LO   (Q_B_HI + 2 * Q_BBYTES)        // 33280
#define Q_TOTAL  (Q_B_LO + 2 * Q_BBYTES)        // 41984

// Proj smem (single buffer, round-11 layout)
#define P1_A_HI 0
#define P1_A_LO (128 * P1_APAD * 2)             // 6144
#define P1_B_HI (2 * 128 * P1_APAD * 2)         // 12288
#define P1_B_LO (P1_B_HI + 16 * P1_BPAD * 2)    // 16640
#define P1_TOTAL (P1_B_LO + 16 * P1_BPAD * 2)   // 20992

// Scratch (device globals: allocation-free contract)
__device__ float g_gx[(size_t)T_ * G3H * B_];             // [t][n][b]
__device__ uint32_t g_xp[(size_t)B_ * T_ * I_];           // [b*T+t][i] packed (hi,lo)
__device__ uint32_t g_hhl[(size_t)(T_ + 1) * H_ * B_];    // [slot][k][b] packed (hi,lo)
__device__ float g_gh[(size_t)2 * KSPLIT * G3H * B_];     // [parity][s][n][b]
__device__ unsigned int g_rowflag[NBLK * 32];
__device__ unsigned int g_sliceflag[KSPLIT * 32];

__device__ __forceinline__ uint32_t smem_u32(const void* p) {
    uint32_t a;
    asm("{ .reg .u64 t; cvta.to.shared.u64 t, %1; cvt.u32.u64 %0, t; }"
        : "=r"(a) : "l"(p));
    return a;
}
__device__ __forceinline__ void ldsm_x4(uint32_t* r, uint32_t addr) {
    asm volatile("ldmatrix.sync.aligned.m8n8.x4.shared.b16 {%0,%1,%2,%3}, [%4];"
                 : "=r"(r[0]), "=r"(r[1]), "=r"(r[2]), "=r"(r[3]) : "r"(addr));
}
__device__ __forceinline__ void ldsm_x4_t(uint32_t* r, uint32_t addr) {
    asm volatile("ldmatrix.sync.aligned.m8n8.x4.trans.shared.b16 {%0,%1,%2,%3}, [%4];"
                 : "=r"(r[0]), "=r"(r[1]), "=r"(r[2]), "=r"(r[3]) : "r"(addr));
}
__device__ __forceinline__ void mma_bf16(float* d, const uint32_t* a, const uint32_t* b) {
    asm volatile("mma.sync.aligned.m16n8k16.row.col.f32.bf16.bf16.f32 "
                 "{%0,%1,%2,%3}, {%4,%5,%6,%7}, {%8,%9}, {%0,%1,%2,%3};"
                 : "+f"(d[0]), "+f"(d[1]), "+f"(d[2]), "+f"(d[3])
                 : "r"(a[0]), "r"(a[1]), "r"(a[2]), "r"(a[3]), "r"(b[0]), "r"(b[1]));
}
__device__ __forceinline__ void flag_wait(const unsigned int* p, unsigned int target) {
    unsigned int v;
    do {
        asm volatile("ld.acquire.gpu.global.u32 %0, [%1];" : "=r"(v) : "l"(p) : "memory");
    } while (v < target);
}
__device__ __forceinline__ void flag_arrive(unsigned int* p) {
    asm volatile("red.release.gpu.global.add.u32 [%0], %1;" :: "l"(p), "r"(1u) : "memory");
}
__device__ __forceinline__ float unhl(uint32_t p) {
    return __bfloat162float(__ushort_as_bfloat16((unsigned short)(p & 0xffffu))) +
           __bfloat162float(__ushort_as_bfloat16((unsigned short)(p >> 16)));
}
__device__ __forceinline__ uint32_t packhl(float h) {
    const __nv_bfloat16 hi = __float2bfloat16(h);
    const __nv_bfloat16 lo = __float2bfloat16(h - __bfloat162float(hi));
    return (uint32_t)__bfloat16_as_ushort(hi) | ((uint32_t)__bfloat16_as_ushort(lo) << 16);
}

__global__ void init_kernel() {
    int i = blockIdx.x * blockDim.x + threadIdx.x;
    if (i < H_ * B_) g_hhl[i] = 0u;                // slot 0 = h_{-1} = 0
    if (i < NBLK * 32) g_rowflag[i] = 0u;
    if (i < KSPLIT * 32) g_sliceflag[i] = 0u;
}

// x[b][t][i] fp32 -> packed (hi,lo) bf16 u32
__global__ __launch_bounds__(512) void xconv(const float* __restrict__ x) {
    const size_t idx = (size_t)blockIdx.x * 512 + threadIdx.x;
    if (idx < (size_t)B_ * T_ * I_) g_xp[idx] = packhl(x[idx]);
}

// ---------------------------------------------------------------------------
// Phase-1 bf16 HMMA GEMM, 3-PASS, double-buffered (validated round 14):
// gx[t][n][b] = x @ w_ih^T. Tile 128n x 128bt, grid (24, 256), 512 threads.
// ---------------------------------------------------------------------------
__global__ __launch_bounds__(512) void gemm1_hmma(
    const float* __restrict__ w_ih)   // [3072][1024]
{
    __shared__ char sm[Q_TOTAL];
    const uint32_t smb = smem_u32(sm);
    const int tid = threadIdx.x;
    const int wid = tid >> 5;
    const int lid = tid & 31;
    const int n0 = blockIdx.x * 128;
    const int t0 = blockIdx.y * 2;
    const int wn  = wid >> 1;
    const int wbt = wid & 1;

    const int w_row = tid >> 2;
    const int w_kq  = (tid & 3) * 4;
    const int x_ci  = tid >> 2;
    const int x_kq  = (tid & 3) * 4;
    const int x_b   = x_ci & 63;
    const int x_tt  = x_ci >> 6;
    const float* wp_base = w_ih + (size_t)(n0 + w_row) * I_ + w_kq;
    const uint32_t* xp_base = g_xp + ((size_t)x_b * T_ + (t0 + x_tt)) * I_ + x_kq;

    const uint32_t aA = smb + Q_A_HI +
        (uint32_t)(((wn * 16 + (lid & 15)) * P1_APAD + ((lid >> 4) << 3)) << 1);
    const uint32_t bA = smb + Q_B_HI +
        (uint32_t)(((((lid >> 3) & 1) * 8 + (lid & 7)) * P1_BPAD + wbt * 64 + ((lid >> 4) << 3)) << 1);

    float d[8][4];
#pragma unroll
    for (int nt = 0; nt < 8; ++nt)
#pragma unroll
        for (int q = 0; q < 4; ++q) d[nt][q] = 0.0f;

    auto stage = [&](int buf, const float4& wv, const uint4& xv) {
        __nv_bfloat16* asH = (__nv_bfloat16*)(sm + Q_A_HI + buf * Q_ABYTES);
        __nv_bfloat16* asL = (__nv_bfloat16*)(sm + Q_A_LO + buf * Q_ABYTES);
        __nv_bfloat16* bsH = (__nv_bfloat16*)(sm + Q_B_HI + buf * Q_BBYTES);
        __nv_bfloat16* bsL = (__nv_bfloat16*)(sm + Q_B_LO + buf * Q_BBYTES);
        const float wf[4] = {wv.x, wv.y, wv.z, wv.w};
#pragma unroll
        for (int j = 0; j < 4; ++j) {
            const __nv_bfloat16 hi = __float2bfloat16(wf[j]);
            asH[w_row * P1_APAD + w_kq + j] = hi;
            asL[w_row * P1_APAD + w_kq + j] =
                __float2bfloat16(wf[j] - __bfloat162float(hi));
        }
        const uint32_t xu[4] = {xv.x, xv.y, xv.z, xv.w};
#pragma unroll
        for (int j = 0; j < 4; ++j) {
            bsH[(x_kq + j) * P1_BPAD + x_ci] =
                __ushort_as_bfloat16((unsigned short)(xu[j] & 0xffffu));
            bsL[(x_kq + j) * P1_BPAD + x_ci] =
                __ushort_as_bfloat16((unsigned short)(xu[j] >> 16));
        }
    };

    {
        const float4 wv0 = *(const float4*)(wp_base);
        const uint4  xv0 = *(const uint4*)(xp_base);
        stage(0, wv0, xv0);
    }
    __syncthreads();

    for (int kc = 0; kc < 64; ++kc) {
        float4 wv; uint4 xv;
        const bool more = (kc + 1 < 64);
        if (more) {
            wv = *(const float4*)(wp_base + (kc + 1) * 16);
            xv = *(const uint4*)(xp_base + (kc + 1) * 16);
        }

        const uint32_t aOff = (uint32_t)((kc & 1) * Q_ABYTES);
        const uint32_t bOff = (uint32_t)((kc & 1) * Q_BBYTES);
        uint32_t aH[4], aL[4], bh[16], bl[16];
        ldsm_x4(aH, aA + aOff);
        ldsm_x4(aL, aA + aOff + (Q_A_LO - Q_A_HI));
#pragma unroll
        for (int q = 0; q < 4; ++q) ldsm_x4_t(&bh[q * 4], bA + bOff + q * 32);
#pragma unroll
        for (int q = 0; q < 4; ++q)
            ldsm_x4_t(&bl[q * 4], bA + bOff + (Q_B_LO - Q_B_HI) + q * 32);

#pragma unroll
        for (int nt = 0; nt < 8; ++nt) mma_bf16(d[nt], aH, &bh[nt * 2]);
#pragma unroll
        for (int nt = 0; nt < 8; ++nt) mma_bf16(d[nt], aH, &bl[nt * 2]);
#pragma unroll
        for (int nt = 0; nt < 8; ++nt) mma_bf16(d[nt], aL, &bh[nt * 2]);

        if (more) stage((kc + 1) & 1, wv, xv);
        __syncthreads();
    }

    {
        const int g = lid >> 2;
        const int q = lid & 3;
        const int n = n0 + wn * 16 + g;
        const int tcur = t0 + wbt;
        float* gx0 = g_gx + ((size_t)tcur * G3H + n) * B_;
        float* gx1 = g_gx + ((size_t)tcur * G3H + n + 8) * B_;
#pragma unroll
        for (int nt = 0; nt < 8; ++nt) {
            const int b = nt * 8 + q * 2;
            *(float2*)(gx0 + b) = make_float2(d[nt][0], d[nt][1]);
            *(float2*)(gx1 + b) = make_float2(d[nt][2], d[nt][3]);
        }
    }
}

// ---------------------------------------------------------------------------
// Persistent bf16-MMA recurrence — ROUND-14 structure (validated best).
// Single change: gate reads h_{t-1} from the staged smem planes instead of
// global (bit-identical values; removes a dependent L2 load from the
// post-rowflag critical path).
// ---------------------------------------------------------------------------
extern __shared__ char dynsm[];

__global__ __launch_bounds__(NTHR) void gru_persistent(
    const float* __restrict__ w_hh)   // [3072][1024]
{
    char* sm = dynsm;
    const uint32_t smem_base = smem_u32(sm);
    const int tid = threadIdx.x;
    const int wid = tid >> 5;
    const int lid = tid & 31;
    const int bid = blockIdx.x;
    const int nbk = bid % NBLK;
    const int s   = bid / NBLK;
    const int n0  = nbk * 128;
    const int kbase = (s < 4) ? s * 176 : 704 + (s - 4) * 160;
    const int klen  = (s < 4) ? 176 : 160;
    const int nkt   = klen >> 4;
    const int kpad  = klen + 8;

    {
        __nv_bfloat16* wsH = (__nv_bfloat16*)(sm + SM_A_HI);
        __nv_bfloat16* wsL = (__nv_bfloat16*)(sm + SM_A_LO);
        for (int i = tid; i < 128 * klen; i += NTHR) {
            const int row = i / klen;
            const int k   = i - row * klen;
            const float w = w_hh[(size_t)(n0 + row) * H_ + kbase + k];
            const __nv_bfloat16 hi = __float2bfloat16(w);
            wsH[row * kpad + k] = hi;
            wsL[row * kpad + k] = __float2bfloat16(w - __bfloat162float(hi));
        }
    }

    const int wn = wid >> 1;
    const int wb = wid & 1;
    const uint32_t aAddr0 = smem_base + SM_A_HI +
        (uint32_t)(((wn * 16 + (lid & 15)) * kpad + ((lid >> 4) << 3)) << 1);
    const uint32_t bAddr0 = smem_base + SM_B_HI +
        (uint32_t)(((((lid >> 3) & 1) * 8 + (lid & 7)) * 72 + wb * 32 + ((lid >> 4) << 3)) << 1);
    const uint32_t A_LO_OFF = SM_A_LO - SM_A_HI;
    const uint32_t B_LO_OFF = SM_B_LO - SM_B_HI;

    __nv_bfloat16* hsH = (__nv_bfloat16*)(sm + SM_B_HI);
    __nv_bfloat16* hsL = (__nv_bfloat16*)(sm + SM_B_LO);

    const int nelem = klen * 64;
    const int chunk = (nelem + NBLK - 1) / NBLK;
    const int e_lo = nbk * chunk;
    const int e_hi = (e_lo + chunk < nelem) ? (e_lo + chunk) : nelem;
    const int e0 = e_lo + tid;
    const bool v0 = e0 < e_hi;
    const int j0 = kbase + (e0 >> 6), b0v = e0 & 63;
    const int kl0 = e0 >> 6;                   // local k index within slice
    const int jb_lo = (kbase + (e_lo >> 6)) >> 7;
    const int jb_hi = (kbase + ((e_hi - 1) >> 6)) >> 7;
    const int njb = jb_hi - jb_lo + 1;          // 1..2
    const int nflags = njb * 3;

    for (int t = 0; t < T_; ++t) {
        const int par = t & 1;

        // ---- prefetch gx gate operands (flag-independent)
        float gr0 = 0.f, gz0 = 0.f, gn0 = 0.f;
        {
            const float* gxt = g_gx + (size_t)t * G3H * B_;
            if (v0) {
                gr0 = gxt[(size_t)j0 * B_ + b0v];
                gz0 = gxt[(size_t)(1024 + j0) * B_ + b0v];
                gn0 = gxt[(size_t)(2048 + j0) * B_ + b0v];
            }
        }

        if (tid == 0) flag_wait(&g_sliceflag[s * 32], 24u * (unsigned)t);
        __syncthreads();

        // ---- stage h slice: packed (hi,lo) -> two smem planes
        {
            const uint32_t* hp = g_hhl + (size_t)t * H_ * B_;
            for (int i = tid; i < klen * 32; i += NTHR) {
                const int k  = i >> 5;
                const int bp = (i & 31) << 1;
                const uint2 v = __ldcg((const uint2*)(hp + (size_t)(kbase + k) * B_ + bp));
                *(uint32_t*)&hsH[k * 72 + bp] = __byte_perm(v.x, v.y, 0x5410);
                *(uint32_t*)&hsL[k * 72 + bp] = __byte_perm(v.x, v.y, 0x7632);
            }
        }
        __syncthreads();

        // ---- mainloop: 3 HMMA passes per k16 chunk
        float d[4][4];
#pragma unroll
        for (int nt = 0; nt < 4; ++nt)
#pragma unroll
            for (int q = 0; q < 4; ++q) d[nt][q] = 0.0f;

        for (int kc = 0; kc < nkt; ++kc) {
            uint32_t aH[4], aL[4], bh[8], bl[8];
            const uint32_t aA = aAddr0 + (uint32_t)(kc * 32);
            const uint32_t bA = bAddr0 + (uint32_t)(kc * 2304);
            ldsm_x4(aH, aA);
            ldsm_x4(aL, aA + A_LO_OFF);
            ldsm_x4_t(bh,     bA);
            ldsm_x4_t(bh + 4, bA + 32);
            ldsm_x4_t(bl,     bA + B_LO_OFF);
            ldsm_x4_t(bl + 4, bA + B_LO_OFF + 32);

#pragma unroll
            for (int nt = 0; nt < 4; ++nt) mma_bf16(d[nt], aH, &bh[nt * 2]);
#pragma unroll
            for (int nt = 0; nt < 4; ++nt) mma_bf16(d[nt], aH, &bl[nt * 2]);
#pragma unroll
            for (int nt = 0; nt < 4; ++nt) mma_bf16(d[nt], aL, &bh[nt * 2]);
        }

        // ---- epilogue: D(n,b) -> g_gh[par][s][n][b], then release row flag
        {
            float* gh = g_gh + ((size_t)par * KSPLIT + s) * G3H * B_;
            const int g = lid >> 2;
            const int q = lid & 3;
            const int nb = n0 + wn * 16 + g;
#pragma unroll
            for (int nt = 0; nt < 4; ++nt) {
                const int b = wb * 32 + nt * 8 + q * 2;
                *(float2*)&gh[(size_t)nb * B_ + b]       = make_float2(d[nt][0], d[nt][1]);
                *(float2*)&gh[(size_t)(nb + 8) * B_ + b] = make_float2(d[nt][2], d[nt][3]);
            }
        }
        __syncthreads();
        if (tid == 0) flag_arrive(&g_rowflag[nbk * 32]);

        // ---- lane-parallel wait for the gh rows this CTA's gate slice needs
        if (wid == 0) {
            if (lid < nflags) {
                const int jb = jb_lo + (lid % njb);
                const int g8 = (lid / njb) * 8;
                flag_wait(&g_rowflag[(jb + g8) * 32], 6u * (unsigned)(t + 1));
            }
            __syncwarp();
        }
        __syncthreads();

        // ---- gate: reduce 6 split partials; h_{t-1} read from staged smem
        if (v0) {
            const float* ghp = g_gh + (size_t)par * KSPLIT * G3H * B_;
            uint32_t* hout = g_hhl + (size_t)(t + 1) * H_ * B_;
            float sr = 0.f, sz = 0.f, sn = 0.f;
#pragma unroll
            for (int ss = 0; ss < KSPLIT; ++ss) {
                const float* p = ghp + (size_t)ss * G3H * B_;
                sr += __ldcg(p + (size_t)j0 * B_ + b0v);
                sz += __ldcg(p + (size_t)(1024 + j0) * B_ + b0v);
                sn += __ldcg(p + (size_t)(2048 + j0) * B_ + b0v);
            }
            const float r = 1.0f / (1.0f + expf(-(gr0 + sr)));
            const float z = 1.0f / (1.0f + expf(-(gz0 + sz)));
            const float n = tanhf(gn0 + r * sn);
            // h_{t-1} from smem (bit-identical to global packed values)
            const float hp = __bfloat162float(hsH[kl0 * 72 + b0v]) +
                             __bfloat162float(hsL[kl0 * 72 + b0v]);
            hout[(size_t)j0 * B_ + b0v] = packhl((1.0f - z) * n + z * hp);
        }
        __syncthreads();
        if (tid == 0) flag_arrive(&g_sliceflag[s * 32]);
    }
}

// ---------------------------------------------------------------------------
// Phase-3 bf16 HMMA projection, 3-PASS (validated round 11/14)
// ---------------------------------------------------------------------------
__global__ __launch_bounds__(512) void proj_hmma(
    const float* __restrict__ wp,     // [1024][1024]
    float* __restrict__ out)          // [64][512][1024]
{
    __shared__ char sm[P1_TOTAL];
    const uint32_t smb = smem_u32(sm);
    const int tid = threadIdx.x;
    const int wid = tid >> 5;
    const int lid = tid & 31;
    const int n0 = blockIdx.x * 128;
    const int t0 = blockIdx.y * 2;
    const int wn  = wid >> 1;
    const int wbt = wid & 1;

    __nv_bfloat16* asH = (__nv_bfloat16*)(sm + P1_A_HI);
    __nv_bfloat16* asL = (__nv_bfloat16*)(sm + P1_A_LO);
    __nv_bfloat16* bsH = (__nv_bfloat16*)(sm + P1_B_HI);
    __nv_bfloat16* bsL = (__nv_bfloat16*)(sm + P1_B_LO);

    const int w_row = tid >> 2;
    const int w_kq  = (tid & 3) * 4;
    const float* wp_base = wp + (size_t)(n0 + w_row) * H_ + w_kq;

    const int i0 = tid, i1 = tid + 512;
    const int s_tt0 = i0 >> 9, s_k0 = (i0 >> 5) & 15, s_bp0 = (i0 & 31) << 1;
    const int s_tt1 = i1 >> 9, s_k1 = (i1 >> 5) & 15, s_bp1 = (i1 & 31) << 1;
    const uint32_t* hb0 = g_hhl + (size_t)(t0 + s_tt0 + 1) * H_ * B_ + s_k0 * B_ + s_bp0;
    const uint32_t* hb1 = g_hhl + (size_t)(t0 + s_tt1 + 1) * H_ * B_ + s_k1 * B_ + s_bp1;

    const uint32_t aA = smb + P1_A_HI +
        (uint32_t)(((wn * 16 + (lid & 15)) * P1_APAD + ((lid >> 4) << 3)) << 1);
    const uint32_t bA = smb + P1_B_HI +
        (uint32_t)(((((lid >> 3) & 1) * 8 + (lid & 7)) * P1_BPAD + wbt * 64 + ((lid >> 4) << 3)) << 1);
    const uint32_t A_LO = P1_A_LO - P1_A_HI;
    const uint32_t B_LO = P1_B_LO - P1_B_HI;

    float d[8][4];
#pragma unroll
    for (int nt = 0; nt < 8; ++nt)
#pragma unroll
        for (int q = 0; q < 4; ++q) d[nt][q] = 0.0f;

    float4 wv = *(const float4*)(wp_base);
    uint2  hv0 = __ldcg((const uint2*)hb0);
    uint2  hv1 = __ldcg((const uint2*)hb1);

    for (int kc = 0; kc < 64; ++kc) {
        __syncthreads();
        {
            const float wf[4] = {wv.x, wv.y, wv.z, wv.w};
#pragma unroll
            for (int j = 0; j < 4; ++j) {
                const __nv_bfloat16 hi = __float2bfloat16(wf[j]);
                asH[w_row * P1_APAD + w_kq + j] = hi;
                asL[w_row * P1_APAD + w_kq + j] =
                    __float2bfloat16(wf[j] - __bfloat162float(hi));
            }
            *(uint32_t*)&bsH[s_k0 * P1_BPAD + s_tt0 * 64 + s_bp0] = __byte_perm(hv0.x, hv0.y, 0x5410);
            *(uint32_t*)&bsL[s_k0 * P1_BPAD + s_tt0 * 64 + s_bp0] = __byte_perm(hv0.x, hv0.y, 0x7632);
            *(uint32_t*)&bsH[s_k1 * P1_BPAD + s_tt1 * 64 + s_bp1] = __byte_perm(hv1.x, hv1.y, 0x5410);
            *(uint32_t*)&bsL[s_k1 * P1_BPAD + s_tt1 * 64 + s_bp1] = __byte_perm(hv1.x, hv1.y, 0x7632);
        }
        __syncthreads();
        if (kc + 1 < 64) {
            wv  = *(const float4*)(wp_base + (kc + 1) * 16);
            hv0 = __ldcg((const uint2*)(hb0 + (size_t)(kc + 1) * 16 * B_));
            hv1 = __ldcg((const uint2*)(hb1 + (size_t)(kc + 1) * 16 * B_));
        }

        uint32_t aH[4], aL[4], bh[16], bl[16];
        ldsm_x4(aH, aA);
        ldsm_x4(aL, aA + A_LO);
#pragma unroll
        for (int q = 0; q < 4; ++q) ldsm_x4_t(&bh[q * 4], bA + q * 32);
#pragma unroll
        for (int q = 0; q < 4; ++q) ldsm_x4_t(&bl[q * 4], bA + B_LO + q * 32);

#pragma unroll
        for (int nt = 0; nt < 8; ++nt) mma_bf16(d[nt], aH, &bh[nt * 2]);
#pragma unroll
        for (int nt = 0; nt < 8; ++nt) mma_bf16(d[nt], aH, &bl[nt * 2]);
#pragma unroll
        for (int nt = 0; nt < 8; ++nt) mma_bf16(d[nt], aL, &bh[nt * 2]);
    }

    {
        const int g = lid >> 2;
        const int q = lid & 3;
        const int n = n0 + wn * 16 + g;
        const int tcur = t0 + wbt;
#pragma unroll
        for (int nt = 0; nt < 8; ++nt) {
            const int b = nt * 8 + q * 2;
            out[((size_t)b * T_ + tcur) * H_ + n]           = d[nt][0];
            out[((size_t)(b + 1) * T_ + tcur) * H_ + n]     = d[nt][1];
            out[((size_t)b * T_ + tcur) * H_ + n + 8]       = d[nt][2];
            out[((size_t)(b + 1) * T_ + tcur) * H_ + n + 8] = d[nt][3];
        }
    }
}

// ---------------------------------------------------------------------------
// kernel_launch — 5 graph nodes, graph-capturable, allocation-free.
// Inputs: x[64,512,1024], w_ih[3072,1024], w_hh[3072,1024], w_proj[1024,1024].
// ---------------------------------------------------------------------------
extern "C" void kernel_launch(void* const* d_in, const int* in_sizes, int n_in,
                              void* d_out, int out_size) {
    const float* x      = (const float*)d_in[0];
    const float* w_ih   = (const float*)d_in[1];
    const float* w_hh   = (const float*)d_in[2];
    const float* w_proj = (const float*)d_in[3];
    float* out = (float*)d_out;

    cudaFuncSetAttribute(gru_persistent,
                         cudaFuncAttributeMaxDynamicSharedMemorySize, SM_TOTAL);

    init_kernel<<<(H_ * B_ + 255) / 256, 256>>>();

    // x -> packed bf16 (hi,lo)
    xconv<<<(B_ * T_ * I_) / 512, 512>>>(x);

    // Phase 1 (HMMA 3-pass, double-buffered): gx[t][n][b] = x @ w_ih^T
    {
        dim3 grid(G3H / 128, T_ / 2);
        gemm1_hmma<<<grid, 512>>>(w_ih);
    }

    // Phase 2: whole recurrence, ONE persistent 512-thread kernel (launch #4)
    gru_persistent<<<GRID_P, NTHR, SM_TOTAL>>>(w_hh);

    // Phase 3 (HMMA 3-pass): out[b][t][n] = h[t+1] @ w_proj^T
    {
        dim3 grid(H_ / 128, T_ / 2);
        proj_hmma<<<grid, 512>>>(w_proj, out);
    }
}